// round 8
// baseline (speedup 1.0000x reference)
#include <cuda_runtime.h>
#include <cuda_bf16.h>
#include <stdint.h>

#define Bb 16
#define Qd 2048
#define Kd 2048
#define Fd 128
#define KT 64
#define NT 512

// smem word offsets (uint32 words)
#define W_QS   0                    // [128][68]
#define W_KS   (128*68)             // [64][68]
#define W_VHI  (W_KS + 64*68)       // [32][136]
#define W_VLO  (W_VHI + 32*136)     // [32][136]
#define SMEM_WORDS (W_VLO + 32*136)
#define SMEM_BYTES (SMEM_WORDS*4)
#define W_LP   (128*68 + 64*68)     // lsum kernel: [256] partials
#define SMEM1_BYTES ((W_LP + 256)*4)

#define PACKBF2(r, lo, hi) asm("cvt.rn.bf16x2.f32 %0, %1, %2;" : "=r"(r) : "f"(hi), "f"(lo))
#define EX2(d, x) asm("ex2.approx.f32 %0, %1;" : "=f"(d) : "f"(x))
#define SQRTA(d, x) asm("sqrt.approx.f32 %0, %1;" : "=f"(d) : "f"(x))

__device__ float g_lsum[Bb * Qd];

__device__ __forceinline__ void mma16816(float& c0, float& c1, float& c2, float& c3,
                                         uint32_t a0, uint32_t a1, uint32_t a2, uint32_t a3,
                                         uint32_t b0, uint32_t b1) {
    asm volatile("mma.sync.aligned.m16n8k16.row.col.f32.bf16.bf16.f32 "
        "{%0,%1,%2,%3}, {%4,%5,%6,%7}, {%8,%9}, {%0,%1,%2,%3};"
        : "+f"(c0), "+f"(c1), "+f"(c2), "+f"(c3)
        : "r"(a0), "r"(a1), "r"(a2), "r"(a3), "r"(b0), "r"(b1));
}

extern __shared__ uint32_t smw[];

// ---------------- kernel 1: softmax denominators ----------------
__global__ void __launch_bounds__(NT, 1) lsum_kernel(
    const float* __restrict__ q, const float* __restrict__ k)
{
    const int b = blockIdx.y, q0 = blockIdx.x * 128;
    const int tid = threadIdx.x;
    const int wid = tid >> 5, lane = tid & 31;
    const int gid = lane >> 2, tig = lane & 3;
    const int rg = wid >> 1, kh = wid & 1;       // row-group, k-half

    uint32_t* QS = smw + W_QS;
    uint32_t* KS = smw + W_KS;
    float* LP = (float*)(smw + W_LP);

    const float C1 = 0.12753859788f;   // log2(e)/sqrt(128)
    const float C0 = -23.0831206f;     // -16*log2(e)

    {
        const float* qp = q + ((size_t)b * Qd + q0) * Fd;
        #pragma unroll
        for (int it = 0; it < 16; it++) {
            int widx = tid + it * NT;
            int row = widx >> 6, w = widx & 63;
            float2 t = *(const float2*)(qp + row * Fd + 2 * w);
            uint32_t pw; PACKBF2(pw, t.x, t.y);
            QS[row * 68 + w] = pw;
        }
    }

    const int r0l = rg * 16 + gid;
    const int qb = r0l * 68 + tig;
    float lsum0 = 0.f, lsum1 = 0.f;

    for (int t = 0; t < 32; t++) {
        const int k0 = t * KT;
        {
            const float* kp = k + ((size_t)b * Kd + k0) * Fd;
            #pragma unroll
            for (int it = 0; it < 8; it++) {
                int widx = tid + it * NT;
                int row = widx >> 6, w = widx & 63;
                float2 tt = *(const float2*)(kp + row * Fd + 2 * w);
                uint32_t pw; PACKBF2(pw, tt.x, tt.y);
                KS[row * 68 + w] = pw;
            }
        }
        __syncthreads();

        float sc[4][4];
        #pragma unroll
        for (int j = 0; j < 4; j++)
            #pragma unroll
            for (int c = 0; c < 4; c++) sc[j][c] = 0.f;

        #pragma unroll
        for (int ks = 0; ks < 8; ks++) {
            uint32_t a0 = QS[qb + 8 * ks];
            uint32_t a1 = QS[qb + 8 * 68 + 8 * ks];
            uint32_t a2 = QS[qb + 8 * ks + 4];
            uint32_t a3 = QS[qb + 8 * 68 + 8 * ks + 4];
            #pragma unroll
            for (int j = 0; j < 4; j++) {
                int kb = (8 * (kh * 4 + j) + gid) * 68 + tig + 8 * ks;
                mma16816(sc[j][0], sc[j][1], sc[j][2], sc[j][3],
                         a0, a1, a2, a3, KS[kb], KS[kb + 4]);
            }
        }
        #pragma unroll
        for (int j = 0; j < 4; j++) {
            float e0, e1, e2, e3;
            EX2(e0, fmaf(sc[j][0], C1, C0));
            EX2(e1, fmaf(sc[j][1], C1, C0));
            EX2(e2, fmaf(sc[j][2], C1, C0));
            EX2(e3, fmaf(sc[j][3], C1, C0));
            lsum0 += e0 + e1;
            lsum1 += e2 + e3;
        }
        __syncthreads();
    }

    lsum0 += __shfl_xor_sync(0xffffffffu, lsum0, 1);
    lsum0 += __shfl_xor_sync(0xffffffffu, lsum0, 2);
    lsum1 += __shfl_xor_sync(0xffffffffu, lsum1, 1);
    lsum1 += __shfl_xor_sync(0xffffffffu, lsum1, 2);
    if (tig == 0) {
        LP[(r0l) * 2 + kh]     = lsum0;
        LP[(r0l + 8) * 2 + kh] = lsum1;
    }
    __syncthreads();
    if (tid < 128)
        g_lsum[(size_t)b * Qd + q0 + tid] = LP[tid * 2] + LP[tid * 2 + 1];
}

// ---------------- kernel 2: P = softmax - dist, O = P @ V ----------------
__global__ void __launch_bounds__(NT, 1) alibi_main_kernel(
    const float* __restrict__ q, const float* __restrict__ k, const float* __restrict__ v,
    const float* __restrict__ cq, const float* __restrict__ ck,
    const int* __restrict__ am, const int* __restrict__ alm,
    const float* __restrict__ bias_scale, const float* __restrict__ running_mean,
    float* __restrict__ out)
{
    const int b = blockIdx.y, q0 = blockIdx.x * 128;
    const int tid = threadIdx.x;
    const int wid = tid >> 5, lane = tid & 31;
    const int gid = lane >> 2, tig = lane & 3;
    const int rg = wid >> 1;            // row-group 0..7
    const int fh = (wid & 1) * 64;      // F half (elements)

    uint32_t* QS  = smw + W_QS;
    uint32_t* KS  = smw + W_KS;
    uint32_t* VHI = smw + W_VHI;
    uint32_t* VLO = smw + W_VLO;

    const float dscale = bias_scale[0] / running_mean[0];
    const float C1 = 0.12753859788f;
    const float C0 = -23.0831206f;

    {
        const float* qp = q + ((size_t)b * Qd + q0) * Fd;
        #pragma unroll
        for (int it = 0; it < 16; it++) {
            int widx = tid + it * NT;
            int row = widx >> 6, w = widx & 63;
            float2 t = *(const float2*)(qp + row * Fd + 2 * w);
            uint32_t pw; PACKBF2(pw, t.x, t.y);
            QS[row * 68 + w] = pw;
        }
    }

    const int r0l = rg * 16 + gid;
    const size_t r0g = (size_t)b * Qd + q0 + r0l;
    const size_t r1g = r0g + 8;
    const float cqx0 = cq[2 * r0g], cqy0 = cq[2 * r0g + 1];
    const float cqx1 = cq[2 * r1g], cqy1 = cq[2 * r1g + 1];
    const size_t m0 = r0g * (size_t)Kd, m1 = r1g * (size_t)Kd;
    const float inv0 = 1.f / g_lsum[r0g];
    const float inv1 = 1.f / g_lsum[r1g];

    float acc[8][4];
    #pragma unroll
    for (int jn = 0; jn < 8; jn++)
        #pragma unroll
        for (int c = 0; c < 4; c++) acc[jn][c] = 0.f;

    const int qb = r0l * 68 + tig;

    for (int t = 0; t < 32; t++) {
        const int k0 = t * KT;

        {
            const float* kp = k + ((size_t)b * Kd + k0) * Fd;
            #pragma unroll
            for (int it = 0; it < 8; it++) {
                int widx = tid + it * NT;
                int row = widx >> 6, w = widx & 63;
                float2 tt = *(const float2*)(kp + row * Fd + 2 * w);
                uint32_t pw; PACKBF2(pw, tt.x, tt.y);
                KS[row * 68 + w] = pw;
            }
        }
        {
            const float* vp = v + ((size_t)b * Kd + k0) * Fd;
            #pragma unroll
            for (int it = 0; it < 4; it++) {
                int idx = tid + it * NT;
                int fp = idx & 63, kw = idx >> 6;
                const float* va = vp + (size_t)(2 * kw) * Fd + 2 * fp;
                float2 a = *(const float2*)(va);
                float2 bb = *(const float2*)(va + Fd);
                uint32_t ph0, ph1;
                PACKBF2(ph0, a.x, bb.x);
                PACKBF2(ph1, a.y, bb.y);
                float r0 = a.x  - __uint_as_float(ph0 << 16);
                float r1 = bb.x - __uint_as_float(ph0 & 0xffff0000u);
                float r2 = a.y  - __uint_as_float(ph1 << 16);
                float r3 = bb.y - __uint_as_float(ph1 & 0xffff0000u);
                uint32_t pl0, pl1;
                PACKBF2(pl0, r0, r1);
                PACKBF2(pl1, r2, r3);
                int base = kw * 136 + 2 * fp;
                *(uint2*)(VHI + base) = make_uint2(ph0, ph1);
                *(uint2*)(VLO + base) = make_uint2(pl0, pl1);
            }
        }
        __syncthreads();

        // ---- S = Q @ K^T (full KT per warp; warp pairs redundant) ----
        float sc[8][4];
        #pragma unroll
        for (int j = 0; j < 8; j++)
            #pragma unroll
            for (int c = 0; c < 4; c++) sc[j][c] = 0.f;

        #pragma unroll
        for (int ks = 0; ks < 8; ks++) {
            uint32_t a0 = QS[qb + 8 * ks];
            uint32_t a1 = QS[qb + 8 * 68 + 8 * ks];
            uint32_t a2 = QS[qb + 8 * ks + 4];
            uint32_t a3 = QS[qb + 8 * 68 + 8 * ks + 4];
            #pragma unroll
            for (int j = 0; j < 8; j++) {
                int kb = (8 * j + gid) * 68 + tig + 8 * ks;
                mma16816(sc[j][0], sc[j][1], sc[j][2], sc[j][3],
                         a0, a1, a2, a3, KS[kb], KS[kb + 4]);
            }
        }

        // ---- elementwise: P = (attn?0:e*inv) - (mask?0:dist), split hi/lo ----
        uint32_t Hw0[8], Hw1[8], Lw0[8], Lw1[8];
        #pragma unroll
        for (int j = 0; j < 8; j++) {
            int c0 = k0 + j * 8 + tig * 2;
            float4 ckv = *(const float4*)(ck + ((size_t)b * Kd + c0) * 2);
            int2 a0m = *(const int2*)(am  + m0 + c0);
            int2 a1m = *(const int2*)(am  + m1 + c0);
            int2 l0m = *(const int2*)(alm + m0 + c0);
            int2 l1m = *(const int2*)(alm + m1 + c0);

            float e00, e01, e10, e11;
            EX2(e00, fmaf(sc[j][0], C1, C0));
            EX2(e01, fmaf(sc[j][1], C1, C0));
            EX2(e10, fmaf(sc[j][2], C1, C0));
            EX2(e11, fmaf(sc[j][3], C1, C0));

            float dxa = cqx0 - ckv.x, dya = cqy0 - ckv.y;
            float dxb = cqx0 - ckv.z, dyb = cqy0 - ckv.w;
            float dxc = cqx1 - ckv.x, dyc = cqy1 - ckv.y;
            float dxd = cqx1 - ckv.z, dyd = cqy1 - ckv.w;
            float d00, d01, d10, d11;
            SQRTA(d00, fmaf(dxa, dxa, dya * dya));
            SQRTA(d01, fmaf(dxb, dxb, dyb * dyb));
            SQRTA(d10, fmaf(dxc, dxc, dyc * dyc));
            SQRTA(d11, fmaf(dxd, dxd, dyd * dyd));

            d00 = (a0m.x | l0m.x) ? 0.f : d00 * dscale;
            d01 = (a0m.y | l0m.y) ? 0.f : d01 * dscale;
            d10 = (a1m.x | l1m.x) ? 0.f : d10 * dscale;
            d11 = (a1m.y | l1m.y) ? 0.f : d11 * dscale;

            float p00 = (a0m.x ? 0.f : e00 * inv0) - d00;
            float p01 = (a0m.y ? 0.f : e01 * inv0) - d01;
            float p10 = (a1m.x ? 0.f : e10 * inv1) - d10;
            float p11 = (a1m.y ? 0.f : e11 * inv1) - d11;

            PACKBF2(Hw0[j], p00, p01);
            PACKBF2(Hw1[j], p10, p11);
            float q00 = p00 - __uint_as_float(Hw0[j] << 16);
            float q01 = p01 - __uint_as_float(Hw0[j] & 0xffff0000u);
            float q10 = p10 - __uint_as_float(Hw1[j] << 16);
            float q11 = p11 - __uint_as_float(Hw1[j] & 0xffff0000u);
            PACKBF2(Lw0[j], q00, q01);
            PACKBF2(Lw1[j], q10, q11);
        }

        // ---- acc += Phi@Vhi + Phi@Vlo + Plo@Vhi  (this warp's F half) ----
        #pragma unroll
        for (int jn = 0; jn < 8; jn++) {
            int vb = fh + jn * 8 + gid + tig * 136;
            #pragma unroll
            for (int ks = 0; ks < 4; ks++) {
                int a = vb + ks * 8 * 136;
                uint32_t bh0 = VHI[a], bh1 = VHI[a + 4 * 136];
                uint32_t bl0 = VLO[a], bl1 = VLO[a + 4 * 136];
                mma16816(acc[jn][0], acc[jn][1], acc[jn][2], acc[jn][3],
                         Hw0[2*ks], Hw1[2*ks], Hw0[2*ks+1], Hw1[2*ks+1], bh0, bh1);
                mma16816(acc[jn][0], acc[jn][1], acc[jn][2], acc[jn][3],
                         Hw0[2*ks], Hw1[2*ks], Hw0[2*ks+1], Hw1[2*ks+1], bl0, bl1);
                mma16816(acc[jn][0], acc[jn][1], acc[jn][2], acc[jn][3],
                         Lw0[2*ks], Lw1[2*ks], Lw0[2*ks+1], Lw1[2*ks+1], bh0, bh1);
            }
        }
        __syncthreads();
    }

    float* o0 = out + r0g * Fd + fh + tig * 2;
    float* o1 = out + r1g * Fd + fh + tig * 2;
    #pragma unroll
    for (int jn = 0; jn < 8; jn++) {
        *(float2*)(o0 + jn * 8) = make_float2(acc[jn][0], acc[jn][1]);
        *(float2*)(o1 + jn * 8) = make_float2(acc[jn][2], acc[jn][3]);
    }
}

extern "C" void kernel_launch(void* const* d_in, const int* in_sizes, int n_in,
                              void* d_out, int out_size) {
    const float* q   = (const float*)d_in[0];
    const float* k   = (const float*)d_in[1];
    const float* v   = (const float*)d_in[2];
    const float* cq  = (const float*)d_in[3];
    const float* ck  = (const float*)d_in[4];
    const int* am    = (const int*)d_in[5];
    const int* alm   = (const int*)d_in[6];
    const float* bs  = (const float*)d_in[7];
    const float* rm  = (const float*)d_in[8];
    float* out = (float*)d_out;

    cudaFuncSetAttribute(lsum_kernel,
                         cudaFuncAttributeMaxDynamicSharedMemorySize, SMEM1_BYTES);
    cudaFuncSetAttribute(alibi_main_kernel,
                         cudaFuncAttributeMaxDynamicSharedMemorySize, SMEM_BYTES);

    dim3 grid(Qd / 128, Bb);
    lsum_kernel<<<grid, NT, SMEM1_BYTES>>>(q, k);
    alibi_main_kernel<<<grid, NT, SMEM_BYTES>>>(q, k, v, cq, ck, am, alm, bs, rm, out);
}

// round 9
// speedup vs baseline: 1.4680x; 1.4680x over previous
#include <cuda_runtime.h>
#include <cuda_bf16.h>
#include <stdint.h>

#define Bb 16
#define Qd 2048
#define Kd 2048
#define Fd 128
#define KT 64
#define NT 256

// smem word offsets (uint32 words)
#define W_QS   0                      // [128][68]
#define W_KS   (128*68)               // [64][68]
#define W_VI   (W_KS + 64*68)         // interleaved V: [32 kw][264]
#define SMEM_WORDS (W_VI + 32*264)
#define SMEM_BYTES (SMEM_WORDS*4)
#define SMEM1_BYTES ((128*68 + 64*68)*4)

#define PACKBF2(r, lo, hi) asm("cvt.rn.bf16x2.f32 %0, %1, %2;" : "=r"(r) : "f"(hi), "f"(lo))
#define EX2(d, x) asm("ex2.approx.f32 %0, %1;" : "=f"(d) : "f"(x))
#define SQRTA(d, x) asm("sqrt.approx.f32 %0, %1;" : "=f"(d) : "f"(x))

__device__ float g_lsum[Bb * Qd];

__device__ __forceinline__ void mma16816(float& c0, float& c1, float& c2, float& c3,
                                         uint32_t a0, uint32_t a1, uint32_t a2, uint32_t a3,
                                         uint32_t b0, uint32_t b1) {
    asm volatile("mma.sync.aligned.m16n8k16.row.col.f32.bf16.bf16.f32 "
        "{%0,%1,%2,%3}, {%4,%5,%6,%7}, {%8,%9}, {%0,%1,%2,%3};"
        : "+f"(c0), "+f"(c1), "+f"(c2), "+f"(c3)
        : "r"(a0), "r"(a1), "r"(a2), "r"(a3), "r"(b0), "r"(b1));
}

#define LDSM4(d0, d1, d2, d3, addr) \
    asm volatile("ldmatrix.sync.aligned.m8n8.x4.shared.b16 {%0,%1,%2,%3}, [%4];" \
        : "=r"(d0), "=r"(d1), "=r"(d2), "=r"(d3) : "r"(addr))

extern __shared__ uint32_t smw[];

// ---------------- kernel 1: softmax denominators ----------------
__global__ void __launch_bounds__(NT, 1) lsum_kernel(
    const float* __restrict__ q, const float* __restrict__ k)
{
    const int b = blockIdx.y, q0 = blockIdx.x * 128;
    const int tid = threadIdx.x;
    const int wid = tid >> 5, lane = tid & 31;
    const int gid = lane >> 2, tig = lane & 3;

    uint32_t* QS = smw + W_QS;
    uint32_t* KS = smw + W_KS;

    const float C1 = 0.12753859788f;   // log2(e)/sqrt(128)
    const float C0 = -23.0831206f;     // -16*log2(e)

    {
        const float* qp = q + ((size_t)b * Qd + q0) * Fd;
        #pragma unroll
        for (int it = 0; it < 32; it++) {
            int widx = tid + it * 256;
            int row = widx >> 6, w = widx & 63;
            float2 t = *(const float2*)(qp + row * Fd + 2 * w);
            uint32_t pw; PACKBF2(pw, t.x, t.y);
            QS[row * 68 + w] = pw;
        }
    }

    // ldmatrix lane addressing
    const int lm = lane >> 3, lr = lane & 7;
    const uint32_t qsb = (uint32_t)__cvta_generic_to_shared(QS);
    const uint32_t ksb = (uint32_t)__cvta_generic_to_shared(KS);
    const uint32_t aAddr0 = qsb + (((wid * 16 + ((lm & 1) << 3) + lr) * 68) + ((lm >> 1) << 2)) * 4;
    const uint32_t bAddr0 = ksb + (((((lm >> 1) << 3) + lr) * 68) + ((lm & 1) << 2)) * 4;

    float lsum0 = 0.f, lsum1 = 0.f;

    for (int t = 0; t < 32; t++) {
        const int k0 = t * KT;
        {
            const float* kp = k + ((size_t)b * Kd + k0) * Fd;
            #pragma unroll
            for (int it = 0; it < 16; it++) {
                int widx = tid + it * 256;
                int row = widx >> 6, w = widx & 63;
                float2 tt = *(const float2*)(kp + row * Fd + 2 * w);
                uint32_t pw; PACKBF2(pw, tt.x, tt.y);
                KS[row * 68 + w] = pw;
            }
        }
        __syncthreads();

        float sc[8][4];
        #pragma unroll
        for (int j = 0; j < 8; j++)
            #pragma unroll
            for (int c = 0; c < 4; c++) sc[j][c] = 0.f;

        #pragma unroll
        for (int ks = 0; ks < 8; ks++) {
            uint32_t a0, a1, a2, a3;
            LDSM4(a0, a1, a2, a3, aAddr0 + ks * 32);
            #pragma unroll
            for (int jp = 0; jp < 4; jp++) {
                uint32_t b0, b1, b2, b3;
                LDSM4(b0, b1, b2, b3, bAddr0 + jp * (16 * 68 * 4) + ks * 32);
                mma16816(sc[2*jp][0], sc[2*jp][1], sc[2*jp][2], sc[2*jp][3],
                         a0, a1, a2, a3, b0, b1);
                mma16816(sc[2*jp+1][0], sc[2*jp+1][1], sc[2*jp+1][2], sc[2*jp+1][3],
                         a0, a1, a2, a3, b2, b3);
            }
        }
        #pragma unroll
        for (int j = 0; j < 8; j++) {
            float e0, e1, e2, e3;
            EX2(e0, fmaf(sc[j][0], C1, C0));
            EX2(e1, fmaf(sc[j][1], C1, C0));
            EX2(e2, fmaf(sc[j][2], C1, C0));
            EX2(e3, fmaf(sc[j][3], C1, C0));
            lsum0 += e0 + e1;
            lsum1 += e2 + e3;
        }
        __syncthreads();
    }

    lsum0 += __shfl_xor_sync(0xffffffffu, lsum0, 1);
    lsum0 += __shfl_xor_sync(0xffffffffu, lsum0, 2);
    lsum1 += __shfl_xor_sync(0xffffffffu, lsum1, 1);
    lsum1 += __shfl_xor_sync(0xffffffffu, lsum1, 2);
    if (tig == 0) {
        g_lsum[(size_t)b * Qd + q0 + wid * 16 + gid] = lsum0;
        g_lsum[(size_t)b * Qd + q0 + wid * 16 + gid + 8] = lsum1;
    }
}

// ---------------- kernel 2: P = softmax - dist, O = P @ V ----------------
__global__ void __launch_bounds__(NT, 1) alibi_main_kernel(
    const float* __restrict__ q, const float* __restrict__ k, const float* __restrict__ v,
    const float* __restrict__ cq, const float* __restrict__ ck,
    const int* __restrict__ am, const int* __restrict__ alm,
    const float* __restrict__ bias_scale, const float* __restrict__ running_mean,
    float* __restrict__ out)
{
    const int b = blockIdx.y, q0 = blockIdx.x * 128;
    const int tid = threadIdx.x;
    const int wid = tid >> 5, lane = tid & 31;
    const int gid = lane >> 2, tig = lane & 3;

    uint32_t* QS = smw + W_QS;
    uint32_t* KS = smw + W_KS;
    uint32_t* VI = smw + W_VI;

    const float dscale = bias_scale[0] / running_mean[0];
    const float C1 = 0.12753859788f;
    const float C0 = -23.0831206f;

    {
        const float* qp = q + ((size_t)b * Qd + q0) * Fd;
        #pragma unroll
        for (int it = 0; it < 32; it++) {
            int widx = tid + it * 256;
            int row = widx >> 6, w = widx & 63;
            float2 t = *(const float2*)(qp + row * Fd + 2 * w);
            uint32_t pw; PACKBF2(pw, t.x, t.y);
            QS[row * 68 + w] = pw;
        }
    }

    const int r0l = wid * 16 + gid;
    const size_t r0g = (size_t)b * Qd + q0 + r0l;
    const size_t r1g = r0g + 8;
    const float cqx0 = cq[2 * r0g], cqy0 = cq[2 * r0g + 1];
    const float cqx1 = cq[2 * r1g], cqy1 = cq[2 * r1g + 1];
    const size_t m0 = r0g * (size_t)Kd, m1 = r1g * (size_t)Kd;
    const float inv0 = 1.f / g_lsum[r0g];
    const float inv1 = 1.f / g_lsum[r1g];

    // ldmatrix lane addressing (S phase)
    const int lm = lane >> 3, lr = lane & 7;
    const uint32_t qsb = (uint32_t)__cvta_generic_to_shared(QS);
    const uint32_t ksb = (uint32_t)__cvta_generic_to_shared(KS);
    const uint32_t aAddr0 = qsb + (((wid * 16 + ((lm & 1) << 3) + lr) * 68) + ((lm >> 1) << 2)) * 4;
    const uint32_t bAddr0 = ksb + (((((lm >> 1) << 3) + lr) * 68) + ((lm & 1) << 2)) * 4;

    float acc[16][4];
    #pragma unroll
    for (int jn = 0; jn < 16; jn++)
        #pragma unroll
        for (int c = 0; c < 4; c++) acc[jn][c] = 0.f;

    for (int t = 0; t < 32; t++) {
        const int k0 = t * KT;

        {
            const float* kp = k + ((size_t)b * Kd + k0) * Fd;
            #pragma unroll
            for (int it = 0; it < 16; it++) {
                int widx = tid + it * 256;
                int row = widx >> 6, w = widx & 63;
                float2 tt = *(const float2*)(kp + row * Fd + 2 * w);
                uint32_t pw; PACKBF2(pw, tt.x, tt.y);
                KS[row * 68 + w] = pw;
            }
        }
        {
            // V interleaved hi/lo: VI[kw*264 + f*2 + {0:hi,1:lo}]
            const float* vp = v + ((size_t)b * Kd + k0) * Fd;
            #pragma unroll
            for (int it = 0; it < 8; it++) {
                int idx = tid + it * 256;
                int fp = idx & 63, kw = idx >> 6;
                const float* va = vp + (size_t)(2 * kw) * Fd + 2 * fp;
                float2 a = *(const float2*)(va);
                float2 bb = *(const float2*)(va + Fd);
                uint32_t ph0, ph1;
                PACKBF2(ph0, a.x, bb.x);
                PACKBF2(ph1, a.y, bb.y);
                float r0 = a.x  - __uint_as_float(ph0 << 16);
                float r1 = bb.x - __uint_as_float(ph0 & 0xffff0000u);
                float r2 = a.y  - __uint_as_float(ph1 << 16);
                float r3 = bb.y - __uint_as_float(ph1 & 0xffff0000u);
                uint32_t pl0, pl1;
                PACKBF2(pl0, r0, r1);
                PACKBF2(pl1, r2, r3);
                *(uint4*)(VI + kw * 264 + 4 * fp) = make_uint4(ph0, pl0, ph1, pl1);
            }
        }
        __syncthreads();

        // ---- S = Q @ K^T via ldmatrix ----
        float sc[8][4];
        #pragma unroll
        for (int j = 0; j < 8; j++)
            #pragma unroll
            for (int c = 0; c < 4; c++) sc[j][c] = 0.f;

        #pragma unroll
        for (int ks = 0; ks < 8; ks++) {
            uint32_t a0, a1, a2, a3;
            LDSM4(a0, a1, a2, a3, aAddr0 + ks * 32);
            #pragma unroll
            for (int jp = 0; jp < 4; jp++) {
                uint32_t b0, b1, b2, b3;
                LDSM4(b0, b1, b2, b3, bAddr0 + jp * (16 * 68 * 4) + ks * 32);
                mma16816(sc[2*jp][0], sc[2*jp][1], sc[2*jp][2], sc[2*jp][3],
                         a0, a1, a2, a3, b0, b1);
                mma16816(sc[2*jp+1][0], sc[2*jp+1][1], sc[2*jp+1][2], sc[2*jp+1][3],
                         a0, a1, a2, a3, b2, b3);
            }
        }

        // ---- per k16-chunk: elementwise P, then PV ----
        #pragma unroll
        for (int ks = 0; ks < 4; ks++) {
            uint32_t HA0, HA1, HB0, HB1, LA0, LA1, LB0, LB1;
            #pragma unroll
            for (int jj = 0; jj < 2; jj++) {
                int j = 2 * ks + jj;
                int c0 = k0 + j * 8 + tig * 2;
                float4 ckv = *(const float4*)(ck + ((size_t)b * Kd + c0) * 2);
                int2 a0m = *(const int2*)(am  + m0 + c0);
                int2 a1m = *(const int2*)(am  + m1 + c0);
                int2 l0m = *(const int2*)(alm + m0 + c0);
                int2 l1m = *(const int2*)(alm + m1 + c0);

                float e00, e01, e10, e11;
                EX2(e00, fmaf(sc[j][0], C1, C0));
                EX2(e01, fmaf(sc[j][1], C1, C0));
                EX2(e10, fmaf(sc[j][2], C1, C0));
                EX2(e11, fmaf(sc[j][3], C1, C0));

                float dxa = cqx0 - ckv.x, dya = cqy0 - ckv.y;
                float dxb = cqx0 - ckv.z, dyb = cqy0 - ckv.w;
                float dxc = cqx1 - ckv.x, dyc = cqy1 - ckv.y;
                float dxd = cqx1 - ckv.z, dyd = cqy1 - ckv.w;
                float d00, d01, d10, d11;
                SQRTA(d00, fmaf(dxa, dxa, dya * dya));
                SQRTA(d01, fmaf(dxb, dxb, dyb * dyb));
                SQRTA(d10, fmaf(dxc, dxc, dyc * dyc));
                SQRTA(d11, fmaf(dxd, dxd, dyd * dyd));

                d00 = (a0m.x | l0m.x) ? 0.f : d00 * dscale;
                d01 = (a0m.y | l0m.y) ? 0.f : d01 * dscale;
                d10 = (a1m.x | l1m.x) ? 0.f : d10 * dscale;
                d11 = (a1m.y | l1m.y) ? 0.f : d11 * dscale;

                float p00 = (a0m.x ? 0.f : e00 * inv0) - d00;
                float p01 = (a0m.y ? 0.f : e01 * inv0) - d01;
                float p10 = (a1m.x ? 0.f : e10 * inv1) - d10;
                float p11 = (a1m.y ? 0.f : e11 * inv1) - d11;

                uint32_t h0, h1, l0, l1;
                PACKBF2(h0, p00, p01);
                PACKBF2(h1, p10, p11);
                float q00 = p00 - __uint_as_float(h0 << 16);
                float q01 = p01 - __uint_as_float(h0 & 0xffff0000u);
                float q10 = p10 - __uint_as_float(h1 << 16);
                float q11 = p11 - __uint_as_float(h1 & 0xffff0000u);
                PACKBF2(l0, q00, q01);
                PACKBF2(l1, q10, q11);
                if (jj == 0) { HA0 = h0; HA1 = h1; LA0 = l0; LA1 = l1; }
                else         { HB0 = h0; HB1 = h1; LB0 = l0; LB1 = l1; }
            }

            // acc += Phi@Vhi + Phi@Vlo + Plo@Vhi (this ks chunk)
            const int vbase = tig * 264 + ks * 2112;
            #pragma unroll
            for (int jn = 0; jn < 16; jn++) {
                int a = vbase + (jn * 8 + gid) * 2;
                uint2 u2a = *(const uint2*)(VI + a);          // (bh0, bl0)
                uint2 u2b = *(const uint2*)(VI + a + 1056);   // (bh1, bl1)
                mma16816(acc[jn][0], acc[jn][1], acc[jn][2], acc[jn][3],
                         HA0, HA1, HB0, HB1, u2a.x, u2b.x);
                mma16816(acc[jn][0], acc[jn][1], acc[jn][2], acc[jn][3],
                         HA0, HA1, HB0, HB1, u2a.y, u2b.y);
                mma16816(acc[jn][0], acc[jn][1], acc[jn][2], acc[jn][3],
                         LA0, LA1, LB0, LB1, u2a.x, u2b.x);
            }
        }
        __syncthreads();
    }

    float* o0 = out + r0g * Fd + tig * 2;
    float* o1 = out + r1g * Fd + tig * 2;
    #pragma unroll
    for (int jn = 0; jn < 16; jn++) {
        *(float2*)(o0 + jn * 8) = make_float2(acc[jn][0], acc[jn][1]);
        *(float2*)(o1 + jn * 8) = make_float2(acc[jn][2], acc[jn][3]);
    }
}

extern "C" void kernel_launch(void* const* d_in, const int* in_sizes, int n_in,
                              void* d_out, int out_size) {
    const float* q   = (const float*)d_in[0];
    const float* k   = (const float*)d_in[1];
    const float* v   = (const float*)d_in[2];
    const float* cq  = (const float*)d_in[3];
    const float* ck  = (const float*)d_in[4];
    const int* am    = (const int*)d_in[5];
    const int* alm   = (const int*)d_in[6];
    const float* bs  = (const float*)d_in[7];
    const float* rm  = (const float*)d_in[8];
    float* out = (float*)d_out;

    cudaFuncSetAttribute(lsum_kernel,
                         cudaFuncAttributeMaxDynamicSharedMemorySize, SMEM1_BYTES);
    cudaFuncSetAttribute(alibi_main_kernel,
                         cudaFuncAttributeMaxDynamicSharedMemorySize, SMEM_BYTES);

    dim3 grid(Qd / 128, Bb);
    lsum_kernel<<<grid, NT, SMEM1_BYTES>>>(q, k);
    alibi_main_kernel<<<grid, NT, SMEM_BYTES>>>(q, k, v, cq, ck, am, alm, bs, rm, out);
}